// round 1
// baseline (speedup 1.0000x reference)
#include <cuda_runtime.h>

// QuantumEvolution: B=512 trajectories, M=2048 steps.
// H(b,t) = px*sx + py*sy + (0.5+nz)*sz  (traceless) -> U = exp(-i dt H) is a
// unit quaternion q=(w, v) with w=cos(th), v=sinc(th)*dt*h, th=dt*|h|.
// Cumulative propagator = quaternion prefix product (newer on the LEFT).
// Outputs per t: columns of the quaternion rotation matrix:
//   rho0=|0><0| (Bloch e_z) -> R[:,2], rho1=|+><+| (Bloch e_x) -> R[:,0].

#define TPB    256
#define STEPS  8
#define MSTEPS 2048
#define BREAL  512

__device__ __forceinline__ float4 qmul(float4 a, float4 b) {
    // Hamilton product a*b; quaternion stored as (w, x, y, z) in (x,y,z,w) fields.
    float4 r;
    r.x = a.x * b.x - a.y * b.y - a.z * b.z - a.w * b.w;
    r.y = a.x * b.y + a.y * b.x + a.z * b.w - a.w * b.z;
    r.z = a.x * b.z - a.y * b.w + a.z * b.x + a.w * b.y;
    r.w = a.x * b.w + a.y * b.z - a.z * b.y + a.w * b.x;
    return r;
}

__global__ __launch_bounds__(TPB)
void qe_kernel(const float* __restrict__ noise,
               const float* __restrict__ pulses,
               float* __restrict__ out) {
    const int b   = blockIdx.x;
    const int tid = threadIdx.x;
    const float dt = 1.0f / 2048.0f;
    const int t0 = tid * STEPS;

    // Coalesced vector loads: each thread owns 8 consecutive time steps.
    const float4* p4 = reinterpret_cast<const float4*>(pulses + (size_t)b * MSTEPS * 2 + t0 * 2);
    const float4* n4 = reinterpret_cast<const float4*>(noise  + (size_t)b * MSTEPS     + t0);
    float4 pa = p4[0], pb = p4[1], pc = p4[2], pd = p4[3];
    float4 na = n4[0], nb = n4[1];

    float px[STEPS] = {pa.x, pa.z, pb.x, pb.z, pc.x, pc.z, pd.x, pd.z};
    float py[STEPS] = {pa.y, pa.w, pb.y, pb.w, pc.y, pc.w, pd.y, pd.w};
    float nz[STEPS] = {na.x, na.y, na.z, na.w, nb.x, nb.y, nb.z, nb.w};

    // Local inclusive quaternion prefixes (newer step multiplies on the left).
    float4 L[STEPS];
    float4 q = make_float4(1.f, 0.f, 0.f, 0.f);
#pragma unroll
    for (int i = 0; i < STEPS; i++) {
        float hx = px[i], hy = py[i], hz = 0.5f + nz[i];
        float t2 = (dt * dt) * (hx * hx + hy * hy + hz * hz);   // theta^2, <= ~1.5e-5
        // cos(theta) and dt*sinc(theta): Taylor in theta^2, exact to fp32 here.
        float c = 1.f - t2 * (0.5f - t2 * (1.f / 24.f));
        float k = dt * (1.f - t2 * ((1.f / 6.f) - t2 * (1.f / 120.f)));
        float4 u = make_float4(c, k * hx, k * hy, k * hz);
        q = qmul(u, q);
        L[i] = q;
    }

    // Block-level inclusive scan of per-thread chunk products (Hillis-Steele).
    __shared__ float4 s[TPB];
    s[tid] = q;
    __syncthreads();
#pragma unroll
    for (int off = 1; off < TPB; off <<= 1) {
        float4 v = s[tid];
        float4 o;
        if (tid >= off) o = s[tid - off];
        __syncthreads();
        if (tid >= off) v = qmul(v, o);   // newer range on the left
        s[tid] = v;
        __syncthreads();
    }
    float4 E = make_float4(1.f, 0.f, 0.f, 0.f);   // exclusive prefix for this chunk
    if (tid > 0) E = s[tid - 1];

    // Compose global prefixes and emit the 6 expectation values per step.
    float obuf[STEPS * 6];
#pragma unroll
    for (int i = 0; i < STEPS; i++) {
        float4 P = qmul(L[i], E);
        float w = P.x, x = P.y, y = P.z, z = P.w;
        obuf[i * 6 + 0] = 2.f * (x * z + w * y);          // rho0, sx
        obuf[i * 6 + 1] = 2.f * (y * z - w * x);          // rho0, sy
        obuf[i * 6 + 2] = 1.f - 2.f * (x * x + y * y);    // rho0, sz
        obuf[i * 6 + 3] = 1.f - 2.f * (y * y + z * z);    // rho1, sx
        obuf[i * 6 + 4] = 2.f * (x * y + w * z);          // rho1, sy
        obuf[i * 6 + 5] = 2.f * (x * z - w * y);          // rho1, sz
    }

    // 48 contiguous floats per thread -> 12 aligned float4 stores (192 B runs).
    float4* o4 = reinterpret_cast<float4*>(out + ((size_t)b * MSTEPS + t0) * 6);
#pragma unroll
    for (int j = 0; j < 12; j++) o4[j] = reinterpret_cast<const float4*>(obuf)[j];
}

extern "C" void kernel_launch(void* const* d_in, const int* in_sizes, int n_in,
                              void* d_out, int out_size) {
    const float* noise  = (const float*)d_in[0];   // [512, 2048, 1]
    const float* pulses = (const float*)d_in[1];   // [512, 2048, 2]
    if (in_sizes[0] > in_sizes[1]) {               // defensive: order by size
        const float* t = noise; noise = pulses; pulses = t;
    }
    qe_kernel<<<BREAL, TPB>>>(noise, pulses, (float*)d_out);
}